// round 13
// baseline (speedup 1.0000x reference)
#include <cuda_runtime.h>
#include <cuda_fp16.h>
#include <cstdint>

#define NJ      55
#define TILE_M  128
#define BLOCK   128
#define GRID_P  444     // 148 SM x 3 blocks

#define SLAB_FLOATS (32 * NJ)            // 1760 floats per slab
#define SMEM_A      16384
#define SMEM_SLABS  (4 * 2 * SLAB_FLOATS * 4)   // 56320
#define SMEM_PTS    (4 * 2 * 96 * 4)            // 3072
#define SMEM_TOTAL  (SMEM_A + SMEM_SLABS + SMEM_PTS)  // 75776

__device__ __forceinline__ uint32_t smem_u32(const void* p) {
    uint32_t a;
    asm("{ .reg .u64 t; cvta.to.shared.u64 t, %1; cvt.u32.u64 %0, t; }" : "=r"(a) : "l"(p));
    return a;
}
__device__ __forceinline__ void ldsm_x4(uint32_t* r, uint32_t addr) {
    asm volatile("ldmatrix.sync.aligned.m8n8.x4.shared.b16 {%0,%1,%2,%3}, [%4];"
                 : "=r"(r[0]), "=r"(r[1]), "=r"(r[2]), "=r"(r[3]) : "r"(addr));
}
__device__ __forceinline__ void mma16816(float* d, const uint32_t* a, uint32_t b0, uint32_t b1) {
    asm volatile("mma.sync.aligned.m16n8k16.row.col.f32.f16.f16.f32 "
                 "{%0,%1,%2,%3}, {%4,%5,%6,%7}, {%8,%9}, {%0,%1,%2,%3};"
                 : "+f"(d[0]), "+f"(d[1]), "+f"(d[2]), "+f"(d[3])
                 : "r"(a[0]), "r"(a[1]), "r"(a[2]), "r"(a[3]), "r"(b0), "r"(b1));
}
__device__ __forceinline__ uint32_t swb(uint32_t b, int r) {
    return (b & 15u) | ((((b >> 4) ^ (uint32_t)(r & 7)) & 7u) << 4);
}
__device__ __forceinline__ void cpa16(uint32_t d, const void* s) {
    asm volatile("cp.async.cg.shared.global [%0], [%1], 16;" :: "r"(d), "l"(s) : "memory");
}
__device__ __forceinline__ void cpa4(uint32_t d, const void* s) {
    asm volatile("cp.async.ca.shared.global [%0], [%1], 4;" :: "r"(d), "l"(s) : "memory");
}
__device__ __forceinline__ uint32_t packh2(float a, float b) {
    __half2 p = __floats2half2_rn(a, b);
    return *(uint32_t*)&p;
}

// stage one warp's 32 weight rows + 32 points; ALWAYS commits a group
__device__ __forceinline__ void stage_tile(const float* __restrict__ weights,
                                           const float* __restrict__ points,
                                           float* slab, float* pts,
                                           long gv0, long N, int lane, int active)
{
    if (active) {
        long rem = N - gv0;
        if (rem > 0) {
            uint32_t d = smem_u32(slab);
            if (rem >= 32) {
                const float4* s = (const float4*)(weights + gv0 * NJ);  // 32|gv0 -> aligned
                #pragma unroll 2
                for (int i = lane; i < (32 * NJ) / 4; i += 32)
                    cpa16(d + 16u * i, s + i);
            } else {
                int nf = (int)rem * NJ;
                int nc = nf >> 2;
                const float4* s = (const float4*)(weights + gv0 * NJ);
                for (int i = lane; i < nc; i += 32) cpa16(d + 16u * i, s + i);
                for (int i = 4 * nc + lane; i < nf; i += 32)
                    cpa4(d + 4u * i, weights + gv0 * NJ + i);
            }
            long remp = rem > 32 ? 32 : rem;
            uint32_t dp = smem_u32(pts);
            int nf = (int)remp * 3;
            int nc = nf >> 2;
            const float4* s = (const float4*)(points + 3 * gv0);
            for (int i = lane; i < nc; i += 32) cpa16(dp + 16u * i, s + i);
            for (int i = 4 * nc + lane; i < nf; i += 32)
                cpa4(dp + 4u * i, points + 3 * gv0 + i);
        }
    }
    asm volatile("cp.async.commit_group;" ::: "memory");
}

extern __shared__ __align__(1024) char dyn_smem[];

__global__ __launch_bounds__(BLOCK)
void lbs_hmma_kernel(const float* __restrict__ points,
                     const float* __restrict__ weights,
                     const float* __restrict__ se3,
                     float* __restrict__ out,
                     int N, int n_tiles)
{
    __half* s_A    = (__half*)dyn_smem;                          // 16 KB
    float*  s_slab = (float*)(dyn_smem + SMEM_A);                // 8 slabs
    float*  s_pts  = (float*)(dyn_smem + SMEM_A + SMEM_SLABS);   // 8 pt bufs

    const int tid  = threadIdx.x;
    const int wid  = tid >> 5;
    const int lane = tid & 31;

    const uint32_t a_base = smem_u32(s_A);

    // ---- build B (hi/lo SE3 rows 0..2, n=r*4+c) in slab region, hoist to regs ----
    uint32_t BH[4][4], BL[4][4];
    {
        __half* b0 = (__half*)s_slab;            // [16][64] transient
        __half* b1 = (__half*)s_slab + 16 * 64;
        for (int idx = tid; idx < 16 * 64; idx += BLOCK) {
            int n = idx >> 6;
            int k = idx & 63;
            float v = (k < NJ && n < 12) ? se3[k * 16 + n] : 0.0f;
            __half hh = __float2half_rn(v);
            __half hl = __float2half_rn(v - __half2float(hh));
            uint32_t off = (uint32_t)(n * 128 + 2 * k);
            off ^= ((off >> 3) & 0x70);
            *(__half*)((char*)b0 + off) = hh;
            *(__half*)((char*)b1 + off) = hl;
        }
        __syncthreads();
        const uint32_t b0b = smem_u32(b0), b1b = smem_u32(b1);
        int nrow = (lane & 7) + (((lane >> 4) & 1) << 3);
        #pragma unroll
        for (int chunk = 0; chunk < 4; chunk++) {
            uint32_t c = (uint32_t)(chunk * 32) + (((uint32_t)(lane >> 3) & 1) << 4);
            uint32_t boff = (uint32_t)nrow * 128 + (c ^ ((uint32_t)(nrow & 7) << 4));
            ldsm_x4(BH[chunk], b0b + boff);
            ldsm_x4(BL[chunk], b1b + boff);
        }
        __syncthreads();   // frags in regs; slab region free for staging
    }

    float* slab[2] = { s_slab + (wid * 2 + 0) * SLAB_FLOATS,
                       s_slab + (wid * 2 + 1) * SLAB_FLOATS };
    float* ptsb[2] = { s_pts + (wid * 2 + 0) * 96,
                       s_pts + (wid * 2 + 1) * 96 };

    const long G = gridDim.x;
    const long t0 = blockIdx.x;

    // ---- prologue: 2-deep prefetch ----
    stage_tile(weights, points, slab[0], ptsb[0],
               t0 * TILE_M + wid * 32, N, lane, t0 < n_tiles);
    stage_tile(weights, points, slab[1], ptsb[1],
               (t0 + G) * TILE_M + wid * 32, N, lane, t0 + G < n_tiles);

    int buf = 0;
    for (long tile = t0; tile < n_tiles; tile += G, buf ^= 1) {
        const long gv0 = tile * TILE_M + wid * 32;

        // ---- wait this tile's group (1 group — next tile's — stays pending) ----
        asm volatile("cp.async.wait_group 1;" ::: "memory");
        __syncwarp();

        // ---- convert own row to packed fp16; grab own point ----
        uint32_t h[28];
        float px, py, pz;
        {
            const float* rp = slab[buf] + lane * NJ;
            #pragma unroll
            for (int q = 0; q < 27; q++)
                h[q] = packh2(rp[2 * q], rp[2 * q + 1]);
            h[27] = packh2(rp[54], 0.0f);
            const float* pp = ptsb[buf] + 3 * lane;
            px = pp[0]; py = pp[1]; pz = pp[2];
        }
        __syncwarp();   // all buf reads done before reissue overwrites it

        // ---- reissue this buffer for tile + 2G ----
        stage_tile(weights, points, slab[buf], ptsb[buf],
                   (tile + 2 * G) * TILE_M + wid * 32, N, lane,
                   tile + 2 * G < n_tiles);

        // ---- repack regs -> swizzled A tile (K zero-padded to 64) ----
        {
            const uint32_t rowbase = a_base + (uint32_t)(wid * 32 + lane) * 128;
            const uint32_t xr = (uint32_t)(lane & 7) << 4;
            #pragma unroll
            for (int b = 0; b < 8; b++) {
                uint32_t h0 = (4 * b + 0 < 28) ? h[4 * b + 0] : 0u;
                uint32_t h1 = (4 * b + 1 < 28) ? h[4 * b + 1] : 0u;
                uint32_t h2 = (4 * b + 2 < 28) ? h[4 * b + 2] : 0u;
                uint32_t h3 = (4 * b + 3 < 28) ? h[4 * b + 3] : 0u;
                uint32_t ad = rowbase + (((uint32_t)(b * 16)) ^ xr);
                asm volatile("st.shared.v4.b32 [%0], {%1,%2,%3,%4};"
                             :: "r"(ad), "r"(h0), "r"(h1), "r"(h2), "r"(h3) : "memory");
            }
        }
        __syncwarp();

        // ---- MMA: D[32x16] = A_warp[32x64] * (Bh + Bl)^T, B from registers ----
        float d[4][4];
        #pragma unroll
        for (int i = 0; i < 4; i++)
            #pragma unroll
            for (int q = 0; q < 4; q++) d[i][q] = 0.0f;

        #pragma unroll
        for (int chunk = 0; chunk < 4; chunk++) {
            uint32_t a0[4], a1[4];
            {
                int rowa = wid * 32 + (lane & 15);
                uint32_t c = (uint32_t)(chunk * 32) + (((uint32_t)lane >> 4) << 4);
                uint32_t ad = a_base + (uint32_t)rowa * 128 + (c ^ ((uint32_t)(rowa & 7) << 4));
                ldsm_x4(a0, ad);
                ldsm_x4(a1, ad + 16 * 128);
            }
            mma16816(d[0], a0, BH[chunk][0], BH[chunk][1]);
            mma16816(d[1], a0, BH[chunk][2], BH[chunk][3]);
            mma16816(d[2], a1, BH[chunk][0], BH[chunk][1]);
            mma16816(d[3], a1, BH[chunk][2], BH[chunk][3]);
            mma16816(d[0], a0, BL[chunk][0], BL[chunk][1]);
            mma16816(d[1], a0, BL[chunk][2], BL[chunk][3]);
            mma16816(d[2], a1, BL[chunk][0], BL[chunk][1]);
            mma16816(d[3], a1, BL[chunk][2], BL[chunk][3]);
        }

        // ---- D exchange through the (now dead) A region, swizzled ----
        char* awarp = (char*)s_A + (wid * 32) * 128;
        {
            int r0 = lane >> 2;
            int cq = 2 * (lane & 3);
            #pragma unroll
            for (int mt = 0; mt < 2; mt++) {
                #pragma unroll
                for (int nt = 0; nt < 2; nt++) {
                    float* dd = d[mt * 2 + nt];
                    int rr = mt * 16 + r0;
                    uint32_t cb = (uint32_t)(nt * 8 + cq) * 4;
                    *(float2*)(awarp + rr * 128 + swb(cb, rr))
                        = make_float2(dd[0], dd[1]);
                    *(float2*)(awarp + (rr + 8) * 128 + swb(cb, rr + 8))
                        = make_float2(dd[2], dd[3]);
                }
            }
        }
        __syncwarp();

        // ---- epilogue: out = A3x4 * [p;1] (points already in regs) ----
        long v = gv0 + lane;
        if (v < N) {
            float4 q0 = *(float4*)(awarp + lane * 128 + swb(0u,  lane));
            float4 q1 = *(float4*)(awarp + lane * 128 + swb(16u, lane));
            float4 q2 = *(float4*)(awarp + lane * 128 + swb(32u, lane));
            out[3 * v + 0] = fmaf(q0.x, px, fmaf(q0.y, py, fmaf(q0.z, pz, q0.w)));
            out[3 * v + 1] = fmaf(q1.x, px, fmaf(q1.y, py, fmaf(q1.z, pz, q1.w)));
            out[3 * v + 2] = fmaf(q2.x, px, fmaf(q2.y, py, fmaf(q2.z, pz, q2.w)));
        }
        __syncwarp();   // exchange reads done before next iter's repack overwrites A
    }
}

extern "C" void kernel_launch(void* const* d_in, const int* in_sizes, int n_in,
                              void* d_out, int out_size)
{
    const int N = out_size / 3;
    const float* points = nullptr;
    const float* weights = nullptr;
    const float* se3 = nullptr;

    for (int i = 0; i < n_in; i++) {
        long sz = in_sizes[i];
        if (sz == (long)NJ * 16)      se3 = (const float*)d_in[i];
        else if (sz == (long)N * NJ)  weights = (const float*)d_in[i];
        else if (sz == (long)N * 3)   points = (const float*)d_in[i];
    }

    cudaFuncSetAttribute(lbs_hmma_kernel,
                         cudaFuncAttributeMaxDynamicSharedMemorySize, SMEM_TOTAL);

    int n_tiles = (N + TILE_M - 1) / TILE_M;
    int grid = n_tiles < GRID_P ? n_tiles : GRID_P;
    lbs_hmma_kernel<<<grid, BLOCK, SMEM_TOTAL>>>(points, weights, se3,
                                                 (float*)d_out, N, n_tiles);
}

// round 14
// speedup vs baseline: 1.0142x; 1.0142x over previous
#include <cuda_runtime.h>
#include <cuda_fp16.h>
#include <cstdint>

#define NJ      55
#define TILE_M  128
#define BLOCK   128
#define GRID_P  740     // 148 SM x 5 blocks
#define AS      112     // A-tile row stride in bytes (56 halves)

__device__ __forceinline__ uint32_t smem_u32(const void* p) {
    uint32_t a;
    asm("{ .reg .u64 t; cvta.to.shared.u64 t, %1; cvt.u32.u64 %0, t; }" : "=r"(a) : "l"(p));
    return a;
}
__device__ __forceinline__ void ldsm_x4(uint32_t* r, uint32_t addr) {
    asm volatile("ldmatrix.sync.aligned.m8n8.x4.shared.b16 {%0,%1,%2,%3}, [%4];"
                 : "=r"(r[0]), "=r"(r[1]), "=r"(r[2]), "=r"(r[3]) : "r"(addr));
}
__device__ __forceinline__ void ldsm_x2(uint32_t* r, uint32_t addr) {
    asm volatile("ldmatrix.sync.aligned.m8n8.x2.shared.b16 {%0,%1}, [%2];"
                 : "=r"(r[0]), "=r"(r[1]) : "r"(addr));
}
__device__ __forceinline__ void mma16816(float* d, const uint32_t* a, uint32_t b0, uint32_t b1) {
    asm volatile("mma.sync.aligned.m16n8k16.row.col.f32.f16.f16.f32 "
                 "{%0,%1,%2,%3}, {%4,%5,%6,%7}, {%8,%9}, {%0,%1,%2,%3};"
                 : "+f"(d[0]), "+f"(d[1]), "+f"(d[2]), "+f"(d[3])
                 : "r"(a[0]), "r"(a[1]), "r"(a[2]), "r"(a[3]), "r"(b0), "r"(b1));
}
__device__ __forceinline__ void mma1688(float* d, uint32_t a0, uint32_t a1, uint32_t b0) {
    asm volatile("mma.sync.aligned.m16n8k8.row.col.f32.f16.f16.f32 "
                 "{%0,%1,%2,%3}, {%4,%5}, {%6}, {%0,%1,%2,%3};"
                 : "+f"(d[0]), "+f"(d[1]), "+f"(d[2]), "+f"(d[3])
                 : "r"(a0), "r"(a1), "r"(b0));
}
__device__ __forceinline__ void cpa16(uint32_t d, const void* s) {
    asm volatile("cp.async.cg.shared.global [%0], [%1], 16;" :: "r"(d), "l"(s) : "memory");
}
__device__ __forceinline__ void cpa4(uint32_t d, const void* s) {
    asm volatile("cp.async.ca.shared.global [%0], [%1], 4;" :: "r"(d), "l"(s) : "memory");
}
__device__ __forceinline__ uint32_t packh2(float a, float b) {
    __half2 p = __floats2half2_rn(a, b);
    return *(uint32_t*)&p;
}

// stage one warp's 32 weight rows (raw fp32); always commits a group
__device__ __forceinline__ void stage_tile(const float* __restrict__ weights,
                                           float* slab, long gv0, long N, int lane)
{
    long rem = N - gv0;
    if (rem > 0) {
        uint32_t d = smem_u32(slab);
        if (rem >= 32) {
            const float4* s = (const float4*)(weights + gv0 * NJ);  // 32|gv0 -> aligned
            #pragma unroll 2
            for (int i = lane; i < (32 * NJ) / 4; i += 32)
                cpa16(d + 16u * i, s + i);
        } else {
            int nf = (int)rem * NJ;
            int nc = nf >> 2;
            const float4* s = (const float4*)(weights + gv0 * NJ);
            for (int i = lane; i < nc; i += 32) cpa16(d + 16u * i, s + i);
            for (int i = 4 * nc + lane; i < nf; i += 32)
                cpa4(d + 4u * i, weights + gv0 * NJ + i);
        }
    }
    asm volatile("cp.async.commit_group;" ::: "memory");
}

__global__ __launch_bounds__(BLOCK, 5)
void lbs_hmma_kernel(const float* __restrict__ points,
                     const float* __restrict__ weights,
                     const float* __restrict__ se3,
                     float* __restrict__ out,
                     int N, int n_tiles)
{
    // A tile [128 rows][56 halves] = 112B rows, NO swizzle (stride 112 is
    // bank-conflict-free: 28 mod 32 walks the 8 4-bank classes). Per-warp
    // 32-row region reused as flat [32][20]f32 D-exchange after MMA.
    __shared__ __align__(16) __half s_A[TILE_M * 56];      // 14 KB
    __shared__ __align__(16) __half s_B[16 * 56];          // 1.75 KB (single fp16)
    __shared__ __align__(16) float  s_lin[4][32 * NJ];     // 27.5 KB fp32 slabs

    const int tid  = threadIdx.x;
    const int wid  = tid >> 5;
    const int lane = tid & 31;

    const uint32_t a_base = smem_u32(s_A);
    const uint32_t b_base = smem_u32(s_B);

    // ---- build B: SE3 rows 0..2 flattened (n = r*4+c), fp16, [16][56] ----
    for (int idx = tid; idx < 16 * 56; idx += BLOCK) {
        int n = idx / 56;
        int k = idx - 56 * n;
        float v = (k < NJ && n < 12) ? se3[k * 16 + n] : 0.0f;
        s_B[n * 56 + k] = __float2half_rn(v);
    }
    __syncthreads();

    float* slabw = s_lin[wid];

    // ---- prologue: prefetch tile0's slab ----
    int tile = blockIdx.x;
    if (tile < n_tiles)
        stage_tile(weights, slabw, (long)tile * TILE_M + wid * 32, N, lane);

    for (; tile < n_tiles; tile += gridDim.x) {
        const long gv0 = (long)tile * TILE_M + wid * 32;

        // ---- wait this tile's slab; convert own row to packed fp16 ----
        asm volatile("cp.async.wait_group 0;" ::: "memory");
        __syncwarp();

        uint32_t h[28];
        {
            const float* rp = slabw + lane * NJ;
            #pragma unroll
            for (int q = 0; q < 27; q++)
                h[q] = packh2(rp[2 * q], rp[2 * q + 1]);
            h[27] = packh2(rp[54], 0.0f);
        }
        __syncwarp();   // all slab reads done before reissue

        // ---- issue prefetch for next tile ----
        {
            long nt = (long)tile + gridDim.x;
            if (nt < n_tiles)
                stage_tile(weights, slabw, nt * TILE_M + wid * 32, N, lane);
            else
                asm volatile("cp.async.commit_group;" ::: "memory");
        }

        // ---- repack: 28 regs -> unswizzled A tile row (7 x STS.128) ----
        {
            const uint32_t rowbase = a_base + (uint32_t)(wid * 32 + lane) * AS;
            #pragma unroll
            for (int b = 0; b < 7; b++) {
                asm volatile("st.shared.v4.b32 [%0], {%1,%2,%3,%4};"
                             :: "r"(rowbase + 16u * b),
                                "r"(h[4 * b + 0]), "r"(h[4 * b + 1]),
                                "r"(h[4 * b + 2]), "r"(h[4 * b + 3]) : "memory");
            }
        }
        __syncwarp();

        // ---- MMA: D[32x16] = A_warp[32x56] * B^T ; 3 x k16 + 1 x k8 ----
        float d[4][4];
        #pragma unroll
        for (int i = 0; i < 4; i++)
            #pragma unroll
            for (int q = 0; q < 4; q++) d[i][q] = 0.0f;

        // lane mapping for ldmatrix addresses
        const int arow16 = wid * 32 + (lane & 15);       // A: rows, +16B split by lane>>4
        const int brow   = (lane & 7) + (((lane >> 4) & 1) << 3);  // B: n-rows 0..15

        #pragma unroll
        for (int chunk = 0; chunk < 3; chunk++) {
            uint32_t a0[4], a1[4], bb[4];
            uint32_t cbyte = 32u * chunk;                 // 16 half-cols per chunk
            {
                uint32_t ad = a_base + (uint32_t)arow16 * AS + cbyte + 16u * (lane >> 4);
                ldsm_x4(a0, ad);
                ldsm_x4(a1, ad + 16 * AS);
            }
            {
                uint32_t bd = b_base + (uint32_t)brow * 56 * 2 + cbyte + 16u * ((lane >> 3) & 1);
                ldsm_x4(bb, bd);
            }
            mma16816(d[0], a0, bb[0], bb[1]);
            mma16816(d[1], a0, bb[2], bb[3]);
            mma16816(d[2], a1, bb[0], bb[1]);
            mma16816(d[3], a1, bb[2], bb[3]);
        }
        // k8 tail: half-cols 48..55 (bytes 96..111)
        {
            uint32_t a0[2], a1[2], bb[2];
            {
                uint32_t ad = a_base + (uint32_t)(wid * 32 + (lane & 7)
                              + 8 * ((lane >> 3) & 1)) * AS + 96u;
                ldsm_x2(a0, ad);
                ldsm_x2(a1, ad + 16 * AS);
            }
            {
                uint32_t bd = b_base + (uint32_t)((lane & 7) + 8 * ((lane >> 3) & 1)) * 56 * 2 + 96u;
                ldsm_x2(bb, bd);
            }
            mma1688(d[0], a0[0], a0[1], bb[0]);
            mma1688(d[1], a0[0], a0[1], bb[1]);
            mma1688(d[2], a1[0], a1[1], bb[0]);
            mma1688(d[3], a1[0], a1[1], bb[1]);
        }

        // ---- D exchange: flat [32][20] f32 in this warp's (dead) A region ----
        float* dex = (float*)((char*)s_A + (wid * 32) * AS);
        {
            int r0 = lane >> 2;
            int cq = 2 * (lane & 3);
            #pragma unroll
            for (int mt = 0; mt < 2; mt++) {
                #pragma unroll
                for (int nt = 0; nt < 2; nt++) {
                    float* dd = d[mt * 2 + nt];
                    int rr = mt * 16 + r0;
                    int cc = nt * 8 + cq;
                    *(float2*)(dex + rr * 20 + cc)       = make_float2(dd[0], dd[1]);
                    *(float2*)(dex + (rr + 8) * 20 + cc) = make_float2(dd[2], dd[3]);
                }
            }
        }
        __syncwarp();

        // ---- epilogue: out = A3x4 * [p;1] ----
        long v = gv0 + lane;
        if (v < N) {
            float4 q0 = *(float4*)(dex + lane * 20 + 0);
            float4 q1 = *(float4*)(dex + lane * 20 + 4);
            float4 q2 = *(float4*)(dex + lane * 20 + 8);
            float px = points[3 * v + 0];
            float py = points[3 * v + 1];
            float pz = points[3 * v + 2];
            out[3 * v + 0] = fmaf(q0.x, px, fmaf(q0.y, py, fmaf(q0.z, pz, q0.w)));
            out[3 * v + 1] = fmaf(q1.x, px, fmaf(q1.y, py, fmaf(q1.z, pz, q1.w)));
            out[3 * v + 2] = fmaf(q2.x, px, fmaf(q2.y, py, fmaf(q2.z, pz, q2.w)));
        }
        __syncwarp();   // exchange reads done before next iter's repack overwrites A
    }
}

extern "C" void kernel_launch(void* const* d_in, const int* in_sizes, int n_in,
                              void* d_out, int out_size)
{
    const int N = out_size / 3;
    const float* points = nullptr;
    const float* weights = nullptr;
    const float* se3 = nullptr;

    for (int i = 0; i < n_in; i++) {
        long sz = in_sizes[i];
        if (sz == (long)NJ * 16)      se3 = (const float*)d_in[i];
        else if (sz == (long)N * NJ)  weights = (const float*)d_in[i];
        else if (sz == (long)N * 3)   points = (const float*)d_in[i];
    }

    int n_tiles = (N + TILE_M - 1) / TILE_M;
    int grid = n_tiles < GRID_P ? n_tiles : GRID_P;
    lbs_hmma_kernel<<<grid, BLOCK>>>(points, weights, se3, (float*)d_out, N, n_tiles);
}

// round 15
// speedup vs baseline: 1.0468x; 1.0322x over previous
#include <cuda_runtime.h>
#include <cuda_fp16.h>
#include <cstdint>

#define NJ      55
#define TILE_M  128
#define BLOCK   128
#define GRID_P  592     // 148 SM x 4 blocks
#define SLAB_B  (32 * NJ * 4)   // 7040 bytes, 16B-multiple

__device__ __forceinline__ uint32_t smem_u32(const void* p) {
    uint32_t a;
    asm("{ .reg .u64 t; cvta.to.shared.u64 t, %1; cvt.u32.u64 %0, t; }" : "=r"(a) : "l"(p));
    return a;
}
__device__ __forceinline__ void ldsm_x4(uint32_t* r, uint32_t addr) {
    asm volatile("ldmatrix.sync.aligned.m8n8.x4.shared.b16 {%0,%1,%2,%3}, [%4];"
                 : "=r"(r[0]), "=r"(r[1]), "=r"(r[2]), "=r"(r[3]) : "r"(addr));
}
__device__ __forceinline__ void mma16816(float* d, const uint32_t* a, uint32_t b0, uint32_t b1) {
    asm volatile("mma.sync.aligned.m16n8k16.row.col.f32.f16.f16.f32 "
                 "{%0,%1,%2,%3}, {%4,%5,%6,%7}, {%8,%9}, {%0,%1,%2,%3};"
                 : "+f"(d[0]), "+f"(d[1]), "+f"(d[2]), "+f"(d[3])
                 : "r"(a[0]), "r"(a[1]), "r"(a[2]), "r"(a[3]), "r"(b0), "r"(b1));
}
__device__ __forceinline__ uint32_t swb(uint32_t b, int r) {
    return (b & 15u) | ((((b >> 4) ^ (uint32_t)(r & 7)) & 7u) << 4);
}
__device__ __forceinline__ uint32_t packh2(float a, float b) {
    __half2 p = __floats2half2_rn(a, b);
    return *(uint32_t*)&p;
}

// one lane posts the whole 7040B slab via TMA bulk copy, completion -> mbar
__device__ __forceinline__ void stage_bulk(const float* __restrict__ src,
                                           uint32_t dst, uint32_t mbar, int lane)
{
    if (lane == 0) {
        asm volatile("mbarrier.arrive.expect_tx.shared.b64 _, [%0], %1;"
                     :: "r"(mbar), "r"((uint32_t)SLAB_B) : "memory");
        asm volatile("cp.async.bulk.shared::cluster.global.mbarrier::complete_tx::bytes "
                     "[%0], [%1], %2, [%3];"
                     :: "r"(dst), "l"(src), "r"((uint32_t)SLAB_B), "r"(mbar) : "memory");
    }
}

__device__ __forceinline__ void mbar_wait(uint32_t mbar, uint32_t parity)
{
    uint32_t done;
    asm volatile(
        "{\n\t.reg .pred p;\n\t"
        "mbarrier.try_wait.parity.acquire.cta.shared::cta.b64 p, [%1], %2;\n\t"
        "selp.b32 %0, 1, 0, p;\n\t}"
        : "=r"(done) : "r"(mbar), "r"(parity) : "memory");
    if (!done) {
        asm volatile(
            "{\n\t.reg .pred P1;\n\t"
            "W_%=:\n\t"
            "mbarrier.try_wait.parity.acquire.cta.shared::cta.b64 P1, [%0], %1, 0x989680;\n\t"
            "@P1 bra.uni D_%=;\n\t"
            "bra.uni W_%=;\n\t"
            "D_%=:\n\t}"
            :: "r"(mbar), "r"(parity) : "memory");
    }
}

__global__ __launch_bounds__(BLOCK, 4)
void lbs_hmma_kernel(const float* __restrict__ points,
                     const float* __restrict__ weights,
                     const float* __restrict__ se3,
                     float* __restrict__ out,
                     int N, int n_tiles)
{
    // A tile [128][64] fp16 swizzled; per-warp 32-row region doubles as D-exchange
    __shared__ __align__(1024) __half s_A[TILE_M * 64];     // 16 KB
    __shared__ __align__(1024) __half s_B[2][16 * 64];      // 4 KB (hi/lo SE3)
    __shared__ __align__(16)   float  s_lin[4][32 * NJ];    // 28.16 KB fp32 slabs
    __shared__ __align__(8)    uint64_t s_mbar[4];          // per-warp mbarrier

    const int tid  = threadIdx.x;
    const int wid  = tid >> 5;
    const int lane = tid & 31;

    const uint32_t a_base  = smem_u32(s_A);
    const uint32_t b0_base = smem_u32(s_B[0]);
    const uint32_t b1_base = smem_u32(s_B[1]);
    const uint32_t mbar    = smem_u32(&s_mbar[wid]);

    // ---- init mbarriers; build B (hi/lo split of SE3 rows 0..2, n = r*4+c) ----
    if (tid < 4) {
        asm volatile("mbarrier.init.shared.b64 [%0], %1;"
                     :: "r"(smem_u32(&s_mbar[tid])), "r"(1u) : "memory");
    }
    for (int idx = tid; idx < 16 * 64; idx += BLOCK) {
        int n = idx >> 6;
        int k = idx & 63;
        float v = (k < NJ && n < 12) ? se3[k * 16 + n] : 0.0f;
        __half hh = __float2half_rn(v);
        __half hl = __float2half_rn(v - __half2float(hh));
        uint32_t off = (uint32_t)(n * 128 + 2 * k);
        off ^= ((off >> 3) & 0x70);
        *(__half*)((char*)s_B[0] + off) = hh;
        *(__half*)((char*)s_B[1] + off) = hl;
    }
    __syncthreads();

    const uint32_t slab_u32 = smem_u32(s_lin[wid]);
    float* slabw = s_lin[wid];

    // ---- prologue: post tile0's slab ----
    long tile = blockIdx.x;
    {
        long gv0 = tile * TILE_M + wid * 32;
        if (tile < n_tiles && gv0 < N)
            stage_bulk(weights + gv0 * NJ, slab_u32, mbar, lane);
    }

    uint32_t ph = 0;
    for (; tile < n_tiles; tile += gridDim.x) {
        const long gv0 = tile * TILE_M + wid * 32;
        if (gv0 >= N) continue;   // whole warp inactive (only possible on last tile)

        // ---- wait this tile's bulk copy ----
        mbar_wait(mbar, ph);
        ph ^= 1;
        __syncwarp();

        // ---- convert own row to packed fp16 ----
        uint32_t h[28];
        {
            const float* rp = slabw + lane * NJ;
            #pragma unroll
            for (int q = 0; q < 27; q++)
                h[q] = packh2(rp[2 * q], rp[2 * q + 1]);
            h[27] = packh2(rp[54], 0.0f);
        }
        __syncwarp();   // all slab reads done before reissue overwrites it

        // ---- post next tile's slab ----
        {
            long nt = tile + gridDim.x;
            long ngv0 = nt * TILE_M + wid * 32;
            if (nt < n_tiles && ngv0 < N)
                stage_bulk(weights + ngv0 * NJ, slab_u32, mbar, lane);
        }

        // ---- repack regs -> swizzled A tile (K zero-padded to 64) ----
        {
            const uint32_t rowbase = a_base + (uint32_t)(wid * 32 + lane) * 128;
            const uint32_t xr = (uint32_t)(lane & 7) << 4;
            #pragma unroll
            for (int b = 0; b < 8; b++) {
                uint32_t h0 = (4 * b + 0 < 28) ? h[4 * b + 0] : 0u;
                uint32_t h1 = (4 * b + 1 < 28) ? h[4 * b + 1] : 0u;
                uint32_t h2 = (4 * b + 2 < 28) ? h[4 * b + 2] : 0u;
                uint32_t h3 = (4 * b + 3 < 28) ? h[4 * b + 3] : 0u;
                uint32_t ad = rowbase + (((uint32_t)(b * 16)) ^ xr);
                asm volatile("st.shared.v4.b32 [%0], {%1,%2,%3,%4};"
                             :: "r"(ad), "r"(h0), "r"(h1), "r"(h2), "r"(h3) : "memory");
            }
        }
        __syncwarp();

        // ---- MMA: D[32x16] = A_warp[32x64] * (Bh + Bl)^T ----
        float d[4][4];
        #pragma unroll
        for (int i = 0; i < 4; i++)
            #pragma unroll
            for (int q = 0; q < 4; q++) d[i][q] = 0.0f;

        #pragma unroll
        for (int chunk = 0; chunk < 4; chunk++) {
            uint32_t a0[4], a1[4];
            {
                int rowa = wid * 32 + (lane & 15);
                uint32_t c = (uint32_t)(chunk * 32) + (((uint32_t)lane >> 4) << 4);
                uint32_t ad = a_base + (uint32_t)rowa * 128 + (c ^ ((uint32_t)(rowa & 7) << 4));
                ldsm_x4(a0, ad);
                ldsm_x4(a1, ad + 16 * 128);
            }
            uint32_t bh[4], bl[4];
            {
                int nrow = (lane & 7) + (((lane >> 4) & 1) << 3);
                uint32_t c = (uint32_t)(chunk * 32) + (((uint32_t)(lane >> 3) & 1) << 4);
                uint32_t boff = (uint32_t)nrow * 128 + (c ^ ((uint32_t)(nrow & 7) << 4));
                ldsm_x4(bh, b0_base + boff);
                ldsm_x4(bl, b1_base + boff);
            }
            mma16816(d[0], a0, bh[0], bh[1]);
            mma16816(d[1], a0, bh[2], bh[3]);
            mma16816(d[2], a1, bh[0], bh[1]);
            mma16816(d[3], a1, bh[2], bh[3]);
            mma16816(d[0], a0, bl[0], bl[1]);
            mma16816(d[1], a0, bl[2], bl[3]);
            mma16816(d[2], a1, bl[0], bl[1]);
            mma16816(d[3], a1, bl[2], bl[3]);
        }

        // ---- D exchange through the (now dead) A region, swizzled ----
        char* awarp = (char*)s_A + (wid * 32) * 128;
        {
            int r0 = lane >> 2;
            int cq = 2 * (lane & 3);
            #pragma unroll
            for (int mt = 0; mt < 2; mt++) {
                #pragma unroll
                for (int nt = 0; nt < 2; nt++) {
                    float* dd = d[mt * 2 + nt];
                    int rr = mt * 16 + r0;
                    uint32_t cb = (uint32_t)(nt * 8 + cq) * 4;
                    *(float2*)(awarp + rr * 128 + swb(cb, rr))
                        = make_float2(dd[0], dd[1]);
                    *(float2*)(awarp + (rr + 8) * 128 + swb(cb, rr + 8))
                        = make_float2(dd[2], dd[3]);
                }
            }
        }
        __syncwarp();

        // ---- epilogue: out = A3x4 * [p;1] ----
        long v = gv0 + lane;
        if (v < N) {
            float4 q0 = *(float4*)(awarp + lane * 128 + swb(0u,  lane));
            float4 q1 = *(float4*)(awarp + lane * 128 + swb(16u, lane));
            float4 q2 = *(float4*)(awarp + lane * 128 + swb(32u, lane));
            float px = points[3 * v + 0];
            float py = points[3 * v + 1];
            float pz = points[3 * v + 2];
            out[3 * v + 0] = fmaf(q0.x, px, fmaf(q0.y, py, fmaf(q0.z, pz, q0.w)));
            out[3 * v + 1] = fmaf(q1.x, px, fmaf(q1.y, py, fmaf(q1.z, pz, q1.w)));
            out[3 * v + 2] = fmaf(q2.x, px, fmaf(q2.y, py, fmaf(q2.z, pz, q2.w)));
        }
        __syncwarp();   // exchange reads done before next iter's repack overwrites A
    }
}

extern "C" void kernel_launch(void* const* d_in, const int* in_sizes, int n_in,
                              void* d_out, int out_size)
{
    const int N = out_size / 3;
    const float* points = nullptr;
    const float* weights = nullptr;
    const float* se3 = nullptr;

    for (int i = 0; i < n_in; i++) {
        long sz = in_sizes[i];
        if (sz == (long)NJ * 16)      se3 = (const float*)d_in[i];
        else if (sz == (long)N * NJ)  weights = (const float*)d_in[i];
        else if (sz == (long)N * 3)   points = (const float*)d_in[i];
    }

    int n_tiles = (N + TILE_M - 1) / TILE_M;
    int grid = n_tiles < GRID_P ? n_tiles : GRID_P;
    lbs_hmma_kernel<<<grid, BLOCK>>>(points, weights, se3, (float*)d_out, N, n_tiles);
}

// round 17
// speedup vs baseline: 1.0491x; 1.0022x over previous
#include <cuda_runtime.h>
#include <cuda_fp16.h>
#include <cstdint>

#define NJ      55
#define TILE_M  128
#define BLOCK   128
#define GRID_P  592     // 148 SM x 4 blocks
#define SLAB_B  (32 * NJ * 4)   // 7040 bytes, 16B-multiple

__device__ __forceinline__ uint32_t smem_u32(const void* p) {
    uint32_t a;
    asm("{ .reg .u64 t; cvta.to.shared.u64 t, %1; cvt.u32.u64 %0, t; }" : "=r"(a) : "l"(p));
    return a;
}
__device__ __forceinline__ void ldsm_x4(uint32_t* r, uint32_t addr) {
    asm volatile("ldmatrix.sync.aligned.m8n8.x4.shared.b16 {%0,%1,%2,%3}, [%4];"
                 : "=r"(r[0]), "=r"(r[1]), "=r"(r[2]), "=r"(r[3]) : "r"(addr));
}
__device__ __forceinline__ void mma16816(float* d, const uint32_t* a, uint32_t b0, uint32_t b1) {
    asm volatile("mma.sync.aligned.m16n8k16.row.col.f32.f16.f16.f32 "
                 "{%0,%1,%2,%3}, {%4,%5,%6,%7}, {%8,%9}, {%0,%1,%2,%3};"
                 : "+f"(d[0]), "+f"(d[1]), "+f"(d[2]), "+f"(d[3])
                 : "r"(a[0]), "r"(a[1]), "r"(a[2]), "r"(a[3]), "r"(b0), "r"(b1));
}
__device__ __forceinline__ uint32_t swb(uint32_t b, int r) {
    return (b & 15u) | ((((b >> 4) ^ (uint32_t)(r & 7)) & 7u) << 4);
}
__device__ __forceinline__ uint32_t packh2(float a, float b) {
    __half2 p = __floats2half2_rn(a, b);
    return *(uint32_t*)&p;
}

// one lane posts the whole 7040B slab via TMA bulk copy, completion -> mbar
__device__ __forceinline__ void stage_bulk(const float* __restrict__ src,
                                           uint32_t dst, uint32_t mbar, int lane)
{
    if (lane == 0) {
        asm volatile("mbarrier.arrive.expect_tx.shared.b64 _, [%0], %1;"
                     :: "r"(mbar), "r"((uint32_t)SLAB_B) : "memory");
        asm volatile("cp.async.bulk.shared::cluster.global.mbarrier::complete_tx::bytes "
                     "[%0], [%1], %2, [%3];"
                     :: "r"(dst), "l"(src), "r"((uint32_t)SLAB_B), "r"(mbar) : "memory");
    }
}

__device__ __forceinline__ void mbar_wait(uint32_t mbar, uint32_t parity)
{
    uint32_t done;
    asm volatile(
        "{\n\t.reg .pred p;\n\t"
        "mbarrier.try_wait.parity.acquire.cta.shared::cta.b64 p, [%1], %2;\n\t"
        "selp.b32 %0, 1, 0, p;\n\t}"
        : "=r"(done) : "r"(mbar), "r"(parity) : "memory");
    if (!done) {
        asm volatile(
            "{\n\t.reg .pred P1;\n\t"
            "W_%=:\n\t"
            "mbarrier.try_wait.parity.acquire.cta.shared::cta.b64 P1, [%0], %1, 0x989680;\n\t"
            "@P1 bra.uni D_%=;\n\t"
            "bra.uni W_%=;\n\t"
            "D_%=:\n\t}"
            :: "r"(mbar), "r"(parity) : "memory");
    }
}

__global__ __launch_bounds__(BLOCK, 4)
void lbs_hmma_kernel(const float* __restrict__ points,
                     const float* __restrict__ weights,
                     const float* __restrict__ se3,
                     float* __restrict__ out,
                     int N, int n_tiles)
{
    // A tile [128][64] fp16 swizzled; per-warp 32-row region doubles as D-exchange
    __shared__ __align__(1024) __half s_A[TILE_M * 64];     // 16 KB
    __shared__ __align__(1024) __half s_B[16 * 64];         // 2 KB (build area)
    __shared__ __align__(16)   float  s_lin[4][32 * NJ];    // 28.16 KB fp32 slabs
    __shared__ __align__(8)    uint64_t s_mbar[4];          // per-warp mbarrier

    const int tid  = threadIdx.x;
    const int wid  = tid >> 5;
    const int lane = tid & 31;

    const uint32_t a_base = smem_u32(s_A);
    const uint32_t mbar   = smem_u32(&s_mbar[wid]);

    // ---- init mbarriers; build B (fp16 SE3 rows 0..2, n = r*4+c); hoist to regs ----
    if (tid < 4) {
        asm volatile("mbarrier.init.shared.b64 [%0], %1;"
                     :: "r"(smem_u32(&s_mbar[tid])), "r"(1u) : "memory");
    }
    for (int idx = tid; idx < 16 * 64; idx += BLOCK) {
        int n = idx >> 6;
        int k = idx & 63;
        float v = (k < NJ && n < 12) ? se3[k * 16 + n] : 0.0f;
        uint32_t off = (uint32_t)(n * 128 + 2 * k);
        off ^= ((off >> 3) & 0x70);
        *(__half*)((char*)s_B + off) = __float2half_rn(v);
    }
    __syncthreads();

    uint32_t BH[4][4];
    {
        const uint32_t b_base = smem_u32(s_B);
        int nrow = (lane & 7) + (((lane >> 4) & 1) << 3);
        #pragma unroll
        for (int chunk = 0; chunk < 4; chunk++) {
            uint32_t c = (uint32_t)(chunk * 32) + (((uint32_t)(lane >> 3) & 1) << 4);
            uint32_t boff = (uint32_t)nrow * 128 + (c ^ ((uint32_t)(nrow & 7) << 4));
            ldsm_x4(BH[chunk], b_base + boff);
        }
    }

    const uint32_t slab_u32 = smem_u32(s_lin[wid]);
    float* slabw = s_lin[wid];

    // ---- prologue: post tile0's slab ----
    long tile = blockIdx.x;
    {
        long gv0 = tile * TILE_M + wid * 32;
        if (tile < n_tiles && gv0 < N)
            stage_bulk(weights + gv0 * NJ, slab_u32, mbar, lane);
    }

    uint32_t ph = 0;
    for (; tile < n_tiles; tile += gridDim.x) {
        const long gv0 = tile * TILE_M + wid * 32;
        if (gv0 >= N) continue;   // whole warp inactive (only possible on last tile)

        // ---- wait this tile's bulk copy ----
        mbar_wait(mbar, ph);
        ph ^= 1;
        __syncwarp();

        // ---- convert own row to packed fp16 ----
        uint32_t h[28];
        {
            const float* rp = slabw + lane * NJ;
            #pragma unroll
            for (int q = 0; q < 27; q++)
                h[q] = packh2(rp[2 * q], rp[2 * q + 1]);
            h[27] = packh2(rp[54], 0.0f);
        }
        __syncwarp();   // all slab reads done before reissue overwrites it

        // ---- post next tile's slab ----
        {
            long nt = tile + gridDim.x;
            long ngv0 = nt * TILE_M + wid * 32;
            if (nt < n_tiles && ngv0 < N)
                stage_bulk(weights + ngv0 * NJ, slab_u32, mbar, lane);
        }

        // ---- repack regs -> swizzled A tile (K zero-padded to 64) ----
        {
            const uint32_t rowbase = a_base + (uint32_t)(wid * 32 + lane) * 128;
            const uint32_t xr = (uint32_t)(lane & 7) << 4;
            #pragma unroll
            for (int b = 0; b < 8; b++) {
                uint32_t h0 = (4 * b + 0 < 28) ? h[4 * b + 0] : 0u;
                uint32_t h1 = (4 * b + 1 < 28) ? h[4 * b + 1] : 0u;
                uint32_t h2 = (4 * b + 2 < 28) ? h[4 * b + 2] : 0u;
                uint32_t h3 = (4 * b + 3 < 28) ? h[4 * b + 3] : 0u;
                uint32_t ad = rowbase + (((uint32_t)(b * 16)) ^ xr);
                asm volatile("st.shared.v4.b32 [%0], {%1,%2,%3,%4};"
                             :: "r"(ad), "r"(h0), "r"(h1), "r"(h2), "r"(h3) : "memory");
            }
        }
        __syncwarp();

        // ---- MMA: D[32x16] = A_warp[32x64] * B^T (16 MMAs, B from regs) ----
        float d[4][4];
        #pragma unroll
        for (int i = 0; i < 4; i++)
            #pragma unroll
            for (int q = 0; q < 4; q++) d[i][q] = 0.0f;

        #pragma unroll
        for (int chunk = 0; chunk < 4; chunk++) {
            uint32_t a0[4], a1[4];
            {
                int rowa = wid * 32 + (lane & 15);
                uint32_t c = (uint32_t)(chunk * 32) + (((uint32_t)lane >> 4) << 4);
                uint32_t ad = a_base + (uint32_t)rowa * 128 + (c ^ ((uint32_t)(rowa & 7) << 4));
                ldsm_x4(a0, ad);
                ldsm_x4(a1, ad + 16 * 128);
            }
            mma16816(d[0], a0, BH[chunk][0], BH[chunk][1]);
            mma16816(d[1], a0, BH[chunk][2], BH[chunk][3]);
            mma16816(d[2], a1, BH[chunk][0], BH[chunk][1]);
            mma16816(d[3], a1, BH[chunk][2], BH[chunk][3]);
        }

        // ---- D exchange through the (now dead) A region, swizzled ----
        char* awarp = (char*)s_A + (wid * 32) * 128;
        {
            int r0 = lane >> 2;
            int cq = 2 * (lane & 3);
            #pragma unroll
            for (int mt = 0; mt < 2; mt++) {
                #pragma unroll
                for (int nt = 0; nt < 2; nt++) {
                    float* dd = d[mt * 2 + nt];
                    int rr = mt * 16 + r0;
                    uint32_t cb = (uint32_t)(nt * 8 + cq) * 4;
                    *(float2*)(awarp + rr * 128 + swb(cb, rr))
                        = make_float2(dd[0], dd[1]);
                    *(float2*)(awarp + (rr + 8) * 128 + swb(cb, rr + 8))
                        = make_float2(dd[2], dd[3]);
                }
            }
        }
        __syncwarp();

        // ---- epilogue: out = A3x4 * [p;1] ----
        long v = gv0 + lane;
        if (v < N) {
            float4 q0 = *(float4*)(awarp + lane * 128 + swb(0u,  lane));
            float4 q1 = *(float4*)(awarp + lane * 128 + swb(16u, lane));
            float4 q2 = *(float4*)(awarp + lane * 128 + swb(32u, lane));
            float px = points[3 * v + 0];
            float py = points[3 * v + 1];
            float pz = points[3 * v + 2];
            out[3 * v + 0] = fmaf(q0.x, px, fmaf(q0.y, py, fmaf(q0.z, pz, q0.w)));
            out[3 * v + 1] = fmaf(q1.x, px, fmaf(q1.y, py, fmaf(q1.z, pz, q1.w)));
            out[3 * v + 2] = fmaf(q2.x, px, fmaf(q2.y, py, fmaf(q2.z, pz, q2.w)));
        }
        __syncwarp();   // exchange reads done before next iter's repack overwrites A
    }
}

extern "C" void kernel_launch(void* const* d_in, const int* in_sizes, int n_in,
                              void* d_out, int out_size)
{
    const int N = out_size / 3;
    const float* points = nullptr;
    const float* weights = nullptr;
    const float* se3 = nullptr;

    for (int i = 0; i < n_in; i++) {
        long sz = in_sizes[i];
        if (sz == (long)NJ * 16)      se3 = (const float*)d_in[i];
        else if (sz == (long)N * NJ)  weights = (const float*)d_in[i];
        else if (sz == (long)N * 3)   points = (const float*)d_in[i];
    }

    int n_tiles = (N + TILE_M - 1) / TILE_M;
    int grid = n_tiles < GRID_P ? n_tiles : GRID_P;
    lbs_hmma_kernel<<<grid, BLOCK>>>(points, weights, se3, (float*)d_out, N, n_tiles);
}